// round 10
// baseline (speedup 1.0000x reference)
#include <cuda_runtime.h>
#include <cuda_bf16.h>
#include <cuda_fp16.h>
#include <cstdint>

#define MAXN 25000
#define MAXE 200000

// ---------------- device scratch ----------------
__device__ __align__(16) __half   g_xwh[MAXN * 256];  // per-node linear output, fp16 (edge-only consumer)
__device__ __align__(16) float    g_xu[MAXN * 4];     // per-node u-projection
__device__ __align__(16) float    g_h [MAXN * 64];    // hidden features
__device__ __align__(16) float    g_agg[MAXN * 64];   // scatter accumulator
__device__ __align__(16) uint32_t g_w1f[8192];        // W split hi, fragment-major
__device__ __align__(16) uint32_t g_w2f[8192];        // W split lo, fragment-major
__device__ int      g_deg[MAXN];
__device__ float    g_inv[MAXN];
__device__ double   g_stats[128];   // zero-init; reset by finalize last-block
__device__ unsigned g_fincnt;       // zero-init; reset by finalize last-block
__device__ float    g_s[64];
__device__ float    g_t[64];

// ---------------- W split into fragment-major layout ----------------
__device__ __forceinline__ void wsplit_one(const float* __restrict__ W, int d, int idx) {
    int n = idx >> 6, k = idx & 63;
    float v = (k < d) ? __ldg(W + k * 256 + n) : 0.f;
    __nv_bfloat16 hi = __float2bfloat16(v);
    float lo = v - __bfloat162float(hi);
    int kk = k >> 4, rem = k & 15;
    int word = rem >> 3, r2 = rem & 7, tg = r2 >> 1, half = r2 & 1;
    int u32idx = ((((n >> 3) * 4) + kk) * 32 + (n & 7) * 4 + tg) * 2 + word;
    ((__nv_bfloat16*)g_w1f)[u32idx * 2 + half] = hi;
    ((__nv_bfloat16*)g_w2f)[u32idx * 2 + half] = __float2bfloat16(lo);
}

// ---------------- degree ----------------
__global__ void deg_kernel(const int* __restrict__ dst, int E) {
    int i = blockIdx.x * blockDim.x + threadIdx.x;
    if (i < E) atomicAdd(&g_deg[dst[i]], 1);
}
// inv + layer-0 W split
__global__ void inv_kernel(const float* __restrict__ W0, int d0, int N) {
    int i = blockIdx.x * blockDim.x + threadIdx.x;
    if (i < N) g_inv[i] = 1.f / (float)(g_deg[i] + 1);
    if (blockIdx.x < 64) wsplit_one(W0, d0, blockIdx.x * 256 + threadIdx.x);
}

// ---------------- mma.sync bf16 helper ----------------
__device__ __forceinline__ void mma_bf16(float4& d, const uint32_t* a, const uint32_t* b) {
    asm volatile(
        "mma.sync.aligned.m16n8k16.row.col.f32.bf16.bf16.f32 "
        "{%0,%1,%2,%3}, {%4,%5,%6,%7}, {%8,%9}, {%0,%1,%2,%3};"
        : "+f"(d.x), "+f"(d.y), "+f"(d.z), "+f"(d.w)
        : "r"(a[0]), "r"(a[1]), "r"(a[2]), "r"(a[3]), "r"(b[0]), "r"(b[1]));
}

static constexpr int ROWB = 144;   // A smem row stride (bytes)
static constexpr int XST  = 68;    // xs/selfplane row stride (floats)

// ---------------- fused GEMM kernel: tile = 32 nodes x 256 cols ----------------
__global__ __launch_bounds__(256, 3)
void mma_kernel(const float* __restrict__ x, const float* __restrict__ U,
                const float* __restrict__ cvec, int d, int useBN, int N) {
    __shared__ __align__(16) char  sA1[32 * ROWB];
    __shared__ __align__(16) char  sA2[32 * ROWB];
    __shared__ __align__(16) float xs[32 * XST];   // fp32 x' ; reused as selfplane

    int tid  = threadIdx.x;
    int base = blockIdx.x * 32;

    // ---- load x' (BN-folded) into xs ----
    int c4n = d >> 2;
    int cnt = 32 * c4n;
    for (int f = tid; f < cnt; f += 256) {
        int row = f / c4n, c4 = f - row * c4n;
        float4 v = make_float4(0.f, 0.f, 0.f, 0.f);
        if (base + row < N) v = *(const float4*)(x + (size_t)base * d + (size_t)f * 4);
        if (useBN) {
            int c = c4 * 4;
            v.x = v.x * g_s[c]     + g_t[c];
            v.y = v.y * g_s[c + 1] + g_t[c + 1];
            v.z = v.z * g_s[c + 2] + g_t[c + 2];
            v.w = v.w * g_s[c + 3] + g_t[c + 3];
        }
        *(float4*)(xs + row * XST + c4 * 4) = v;
    }
    if (d == 32) {  // zero upper K half
        int row = tid >> 3, c = 32 + (tid & 7) * 4;
        *(float4*)(xs + row * XST + c) = make_float4(0.f, 0.f, 0.f, 0.f);
    }
    __syncthreads();

    // ---- bf16 split of A into smem ----
    {
        int row = tid >> 3, cg = tid & 7;
        float4 v0 = *(float4*)(xs + row * XST + cg * 8);
        float4 v1 = *(float4*)(xs + row * XST + cg * 8 + 4);
        float vv[8] = {v0.x, v0.y, v0.z, v0.w, v1.x, v1.y, v1.z, v1.w};
        uint32_t hiw[4], low[4];
#pragma unroll
        for (int j = 0; j < 4; j++) {
            __nv_bfloat16 h0 = __float2bfloat16(vv[j * 2]);
            __nv_bfloat16 h1 = __float2bfloat16(vv[j * 2 + 1]);
            __nv_bfloat16 l0 = __float2bfloat16(vv[j * 2]     - __bfloat162float(h0));
            __nv_bfloat16 l1 = __float2bfloat16(vv[j * 2 + 1] - __bfloat162float(h1));
            hiw[j] = (uint32_t)*(uint16_t*)&h0 | ((uint32_t)*(uint16_t*)&h1 << 16);
            low[j] = (uint32_t)*(uint16_t*)&l0 | ((uint32_t)*(uint16_t*)&l1 << 16);
        }
        *(uint4*)(sA1 + row * ROWB + cg * 16) = make_uint4(hiw[0], hiw[1], hiw[2], hiw[3]);
        *(uint4*)(sA2 + row * ROWB + cg * 16) = make_uint4(low[0], low[1], low[2], low[3]);
    }

    // ---- xu = x' @ U (warp w: rows w*4..w*4+4) ----
    {
        int w = tid >> 5, lane = tid & 31;
        float4 u0 = __ldg((const float4*)(U + lane * 4));
        float4 u1 = make_float4(0.f, 0.f, 0.f, 0.f);
        if (d == 64) u1 = __ldg((const float4*)(U + (lane + 32) * 4));
#pragma unroll
        for (int t2 = 0; t2 < 4; t2++) {
            int rloc = w * 4 + t2;
            float v0 = xs[rloc * XST + lane];
            float v1 = xs[rloc * XST + 32 + lane];  // zero when d==32
            float4 p;
            p.x = v0 * u0.x + v1 * u1.x;
            p.y = v0 * u0.y + v1 * u1.y;
            p.z = v0 * u0.z + v1 * u1.z;
            p.w = v0 * u0.w + v1 * u1.w;
#pragma unroll
            for (int off = 16; off >= 1; off >>= 1) {
                p.x += __shfl_xor_sync(0xffffffffu, p.x, off);
                p.y += __shfl_xor_sync(0xffffffffu, p.y, off);
                p.z += __shfl_xor_sync(0xffffffffu, p.z, off);
                p.w += __shfl_xor_sync(0xffffffffu, p.w, off);
            }
            if (lane == 0 && base + rloc < N)
                *(float4*)(g_xu + (size_t)(base + rloc) * 4) = p;
        }
    }
    __syncthreads();

    // ---- MMA mainloop ----
    int w = tid >> 5, lane = tid & 31;
    int g = lane >> 2, tg = lane & 3;
    int q = w & 3, r = w >> 2;
    int rblk = r * 16;

    float4 acc[8];
#pragma unroll
    for (int i = 0; i < 8; i++) acc[i] = make_float4(0.f, 0.f, 0.f, 0.f);

#pragma unroll
    for (int kk = 0; kk < 4; kk++) {
        int k0 = kk * 16;
        int ro0 = (rblk + g) * ROWB, ro1 = (rblk + g + 8) * ROWB;
        int kc0 = (k0 + tg * 2) * 2, kc1 = (k0 + 8 + tg * 2) * 2;
        uint32_t a1f[4], a2f[4];
        a1f[0] = *(const uint32_t*)(sA1 + ro0 + kc0);
        a1f[1] = *(const uint32_t*)(sA1 + ro1 + kc0);
        a1f[2] = *(const uint32_t*)(sA1 + ro0 + kc1);
        a1f[3] = *(const uint32_t*)(sA1 + ro1 + kc1);
        a2f[0] = *(const uint32_t*)(sA2 + ro0 + kc0);
        a2f[1] = *(const uint32_t*)(sA2 + ro1 + kc0);
        a2f[2] = *(const uint32_t*)(sA2 + ro0 + kc1);
        a2f[3] = *(const uint32_t*)(sA2 + ro1 + kc1);
#pragma unroll
        for (int nt = 0; nt < 8; nt++) {
            int fidx = (((q * 8 + nt) * 4) + kk) * 32 + lane;
            uint2 B1 = __ldg((const uint2*)g_w1f + fidx);
            uint2 B2 = __ldg((const uint2*)g_w2f + fidx);
            uint32_t b1[2] = {B1.x, B1.y};
            uint32_t b2[2] = {B2.x, B2.y};
            mma_bf16(acc[nt], a1f, b1);
            mma_bf16(acc[nt], a2f, b1);
            mma_bf16(acc[nt], a1f, b2);
        }
    }

    // ---- write xw (fp16) ----
    int row0 = base + rblk + g;
    int row1 = row0 + 8;
#pragma unroll
    for (int nt = 0; nt < 8; nt++) {
        int col = q * 64 + nt * 8 + tg * 2;
        if (row0 < N)
            *(__half2*)(g_xwh + (size_t)row0 * 256 + col) = __floats2half2_rn(acc[nt].x, acc[nt].y);
        if (row1 < N)
            *(__half2*)(g_xwh + (size_t)row1 * 256 + col) = __floats2half2_rn(acc[nt].z, acc[nt].w);
    }

    // ---- self-loop message -> g_agg init (fp32, exact) ----
    float c0 = __ldg(cvec + 0), c1 = __ldg(cvec + 1);
    float c2 = __ldg(cvec + 2), c3 = __ldg(cvec + 3);
    float mx = fmaxf(fmaxf(c0, c1), fmaxf(c2, c3));
    float e0 = __expf(c0 - mx), e1 = __expf(c1 - mx);
    float e2 = __expf(c2 - mx), e3 = __expf(c3 - mx);
    float sinv = 1.f / (e0 + e1 + e2 + e3);
    float aq = (q == 0 ? e0 : q == 1 ? e1 : q == 2 ? e2 : e3) * sinv;

    __syncthreads();  // xs dead -> reuse as selfplane [32][XST]
    {
        int rw = tid >> 3, c = (tid & 7) * 8;
        *(float4*)(xs + rw * XST + c)     = make_float4(0.f, 0.f, 0.f, 0.f);
        *(float4*)(xs + rw * XST + c + 4) = make_float4(0.f, 0.f, 0.f, 0.f);
    }
    __syncthreads();
#pragma unroll
    for (int qq = 0; qq < 4; qq++) {
        if (q == qq) {
#pragma unroll
            for (int nt = 0; nt < 8; nt++) {
                int cl = nt * 8 + tg * 2;
                float2* p0 = (float2*)(xs + (rblk + g) * XST + cl);
                float2* p1 = (float2*)(xs + (rblk + g + 8) * XST + cl);
                float2 v0 = *p0, v1 = *p1;
                v0.x += aq * acc[nt].x; v0.y += aq * acc[nt].y;
                v1.x += aq * acc[nt].z; v1.y += aq * acc[nt].w;
                *p0 = v0; *p1 = v1;
            }
        }
        __syncthreads();
    }
    {
        int rw = tid >> 3, c = (tid & 7) * 8;
        if (base + rw < N) {
            *(float4*)(g_agg + (size_t)(base + rw) * 64 + c)     = *(float4*)(xs + rw * XST + c);
            *(float4*)(g_agg + (size_t)(base + rw) * 64 + c + 4) = *(float4*)(xs + rw * XST + c + 4);
        }
    }
}

// ---------------- edge kernel v2: 8 lanes/edge, lane0-computed softmax + shfl ----------------
__global__ void edge_kernel(const int* __restrict__ src, const int* __restrict__ dst,
                            const float* __restrict__ cvec, int E) {
    int gw   = (blockIdx.x * blockDim.x + threadIdx.x) >> 5;  // warp id
    int lane = threadIdx.x & 31;
    int sub  = lane >> 3;   // edge slot within warp (0..3)
    int j    = lane & 7;    // channel group (8 channels)
    int e = gw * 4 + sub;

    int s = 0, dv = 0;
    float a0 = 0.f, a1 = 0.f, a2 = 0.f, a3 = 0.f;
    if (j == 0 && e < E) {
        s  = __ldg(src + e);
        dv = __ldg(dst + e);
        const float4 us = *(const float4*)(g_xu + s  * 4);
        const float4 ud = *(const float4*)(g_xu + dv * 4);
        float l0 = ud.x - us.x + __ldg(cvec + 0);
        float l1 = ud.y - us.y + __ldg(cvec + 1);
        float l2 = ud.z - us.z + __ldg(cvec + 2);
        float l3 = ud.w - us.w + __ldg(cvec + 3);
        float mx = fmaxf(fmaxf(l0, l1), fmaxf(l2, l3));
        float e0 = __expf(l0 - mx), e1 = __expf(l1 - mx);
        float e2 = __expf(l2 - mx), e3 = __expf(l3 - mx);
        float inv = 1.f / (e0 + e1 + e2 + e3);
        a0 = e0 * inv; a1 = e1 * inv; a2 = e2 * inv; a3 = e3 * inv;
    }
    int bl = sub * 8;  // broadcast source lane
    s  = __shfl_sync(0xffffffffu, s,  bl);
    dv = __shfl_sync(0xffffffffu, dv, bl);
    a0 = __shfl_sync(0xffffffffu, a0, bl);
    a1 = __shfl_sync(0xffffffffu, a1, bl);
    a2 = __shfl_sync(0xffffffffu, a2, bl);
    a3 = __shfl_sync(0xffffffffu, a3, bl);
    if (e >= E) return;

    // lane owns channels [j*8, j*8+8): one uint4 (8 halfs) per head
    const uint4* xwp = (const uint4*)(g_xwh + (size_t)s * 256);
    uint4 u0 = __ldg(xwp + j);          // head 0: uint4 index 0*8 + j
    uint4 u1 = __ldg(xwp + 8 + j);      // head 1
    uint4 u2 = __ldg(xwp + 16 + j);     // head 2
    uint4 u3 = __ldg(xwp + 24 + j);     // head 3

    float m[8];
#pragma unroll
    for (int t = 0; t < 8; t++) m[t] = 0.f;
    {
        const uint32_t* p = &u0.x;
#pragma unroll
        for (int t2 = 0; t2 < 4; t2++) {
            float2 f = __half22float2(*(const __half2*)(p + t2));
            m[t2 * 2]     += a0 * f.x;
            m[t2 * 2 + 1] += a0 * f.y;
        }
    }
    {
        const uint32_t* p = &u1.x;
#pragma unroll
        for (int t2 = 0; t2 < 4; t2++) {
            float2 f = __half22float2(*(const __half2*)(p + t2));
            m[t2 * 2]     += a1 * f.x;
            m[t2 * 2 + 1] += a1 * f.y;
        }
    }
    {
        const uint32_t* p = &u2.x;
#pragma unroll
        for (int t2 = 0; t2 < 4; t2++) {
            float2 f = __half22float2(*(const __half2*)(p + t2));
            m[t2 * 2]     += a2 * f.x;
            m[t2 * 2 + 1] += a2 * f.y;
        }
    }
    {
        const uint32_t* p = &u3.x;
#pragma unroll
        for (int t2 = 0; t2 < 4; t2++) {
            float2 f = __half22float2(*(const __half2*)(p + t2));
            m[t2 * 2]     += a3 * f.x;
            m[t2 * 2 + 1] += a3 * f.y;
        }
    }

    float* aggp = g_agg + (size_t)dv * 64 + j * 8;
    atomicAdd((float4*)aggp,       make_float4(m[0], m[1], m[2], m[3]));
    atomicAdd((float4*)(aggp + 4), make_float4(m[4], m[5], m[6], m[7]));
}

// ---------------- finalize: mean + bias (+relu + BN stats + s/t fold + next W split) ----------------
__global__ void finalize_kernel(const float* __restrict__ b, const float* __restrict__ gvec,
                                const float* __restrict__ bevec, const float* __restrict__ Wnext,
                                float* __restrict__ out, int N, int doStats) {
    if (doStats && blockIdx.x < 64)
        wsplit_one(Wnext, 64, blockIdx.x * 256 + threadIdx.x);

    int c = threadIdx.x & 63;
    int r = threadIdx.x >> 6;
    float bc = __ldg(b + c);
    float ls = 0.f, lq = 0.f;
    int base = blockIdx.x * 64;

#pragma unroll
    for (int j = 0; j < 16; j++) {
        int i = base + r + j * 4;
        if (i >= N) break;
        float v = g_agg[(size_t)i * 64 + c] * g_inv[i] + bc;
        if (doStats) {
            v = fmaxf(v, 0.f);
            out[(size_t)i * 64 + c] = v;
            ls += v;
            lq += v * v;
        } else {
            out[(size_t)i * 64 + c] = v;
        }
    }

    if (doStats) {
        __shared__ double ss[256], sq[256];
        __shared__ int isLast;
        ss[threadIdx.x] = (double)ls; sq[threadIdx.x] = (double)lq;
        __syncthreads();
        if (threadIdx.x < 128) {
            ss[threadIdx.x] += ss[threadIdx.x + 128];
            sq[threadIdx.x] += sq[threadIdx.x + 128];
        }
        __syncthreads();
        if (threadIdx.x < 64) {
            atomicAdd(&g_stats[c],      ss[threadIdx.x] + ss[threadIdx.x + 64]);
            atomicAdd(&g_stats[64 + c], sq[threadIdx.x] + sq[threadIdx.x + 64]);
        }
        __syncthreads();
        if (threadIdx.x == 0) {
            __threadfence();
            unsigned v = atomicAdd(&g_fincnt, 1u);
            isLast = (v == gridDim.x - 1) ? 1 : 0;
        }
        __syncthreads();
        if (isLast) {
            if (threadIdx.x < 64) {
                __threadfence();
                int cc = threadIdx.x;
                double mean = g_stats[cc] / (double)N;
                double var  = g_stats[64 + cc] / (double)N - mean * mean;
                float s = __ldg(gvec + cc) * rsqrtf((float)var + 1e-5f);
                g_s[cc] = s;
                g_t[cc] = __ldg(bevec + cc) - (float)mean * s;
                g_stats[cc] = 0.0;
                g_stats[64 + cc] = 0.0;
            }
            if (threadIdx.x == 0) g_fincnt = 0u;
        }
    }
}

// ---------------- launch ----------------
extern "C" void kernel_launch(void* const* d_in, const int* in_sizes, int n_in,
                              void* d_out, int out_size) {
    const float* x  = (const float*)d_in[0];
    const int*   ei = (const int*)d_in[1];
    const float* W [3] = {(const float*)d_in[2],  (const float*)d_in[6],  (const float*)d_in[10]};
    const float* U [3] = {(const float*)d_in[3],  (const float*)d_in[7],  (const float*)d_in[11]};
    const float* Cv[3] = {(const float*)d_in[4],  (const float*)d_in[8],  (const float*)d_in[12]};
    const float* B [3] = {(const float*)d_in[5],  (const float*)d_in[9],  (const float*)d_in[13]};
    const float* G [2] = {(const float*)d_in[14], (const float*)d_in[16]};
    const float* BE[2] = {(const float*)d_in[15], (const float*)d_in[17]};

    int N = in_sizes[0] / 32;
    int E = in_sizes[1] / 2;
    const int* src = ei;
    const int* dst = ei + E;

    void *p_deg = nullptr, *p_h = nullptr;
    cudaGetSymbolAddress(&p_deg, g_deg);
    cudaGetSymbolAddress(&p_h,   g_h);
    float* hbuf = (float*)p_h;

    cudaMemsetAsync(p_deg, 0, (size_t)N * sizeof(int));
    deg_kernel<<<(E + 255) / 256, 256>>>(dst, E);
    inv_kernel<<<(N + 255) / 256, 256>>>(W[0], 32, N);   // also splits W0

    int mma_blocks  = (N + 31) / 32;
    int edge_blocks = ((size_t)E * 8 + 255) / 256;
    int fin_blocks  = (N + 63) / 64;

    for (int l = 0; l < 3; l++) {
        const float* xin = (l == 0) ? x : hbuf;
        int d = (l == 0) ? 32 : 64;
        mma_kernel<<<mma_blocks, 256>>>(xin, U[l], Cv[l], d, (l > 0) ? 1 : 0, N);
        edge_kernel<<<edge_blocks, 256>>>(src, dst, Cv[l], E);
        if (l < 2) {
            finalize_kernel<<<fin_blocks, 256>>>(B[l], G[l], BE[l], W[l + 1], hbuf, N, 1);
        } else {
            finalize_kernel<<<fin_blocks, 256>>>(B[l], nullptr, nullptr, nullptr, (float*)d_out, N, 0);
        }
    }
}

// round 11
// speedup vs baseline: 1.0142x; 1.0142x over previous
#include <cuda_runtime.h>
#include <cuda_bf16.h>
#include <cuda_fp16.h>
#include <cstdint>

#define MAXN 25000
#define MAXE 200000

// ---------------- device scratch ----------------
__device__ __align__(16) __half   g_xwh[MAXN * 256];  // per-node linear output, fp16 (edge-only consumer)
__device__ __align__(16) float    g_xu[MAXN * 4];     // per-node u-projection
__device__ __align__(16) float    g_h [MAXN * 64];    // hidden features
__device__ __align__(16) float    g_agg[MAXN * 64];   // scatter accumulator
__device__ __align__(16) uint32_t g_w1f[8192];        // W split hi, fragment-major
__device__ __align__(16) uint32_t g_w2f[8192];        // W split lo, fragment-major
__device__ int      g_deg[MAXN];
__device__ float    g_inv[MAXN];
__device__ double   g_stats[128];   // zero-init; reset by finalize last-block
__device__ unsigned g_fincnt;       // zero-init; reset by finalize last-block
__device__ float    g_s[64];
__device__ float    g_t[64];

// ---------------- W split into fragment-major layout ----------------
__device__ __forceinline__ void wsplit_one(const float* __restrict__ W, int d, int idx) {
    int n = idx >> 6, k = idx & 63;
    float v = (k < d) ? __ldg(W + k * 256 + n) : 0.f;
    __nv_bfloat16 hi = __float2bfloat16(v);
    float lo = v - __bfloat162float(hi);
    int kk = k >> 4, rem = k & 15;
    int word = rem >> 3, r2 = rem & 7, tg = r2 >> 1, half = r2 & 1;
    int u32idx = ((((n >> 3) * 4) + kk) * 32 + (n & 7) * 4 + tg) * 2 + word;
    ((__nv_bfloat16*)g_w1f)[u32idx * 2 + half] = hi;
    ((__nv_bfloat16*)g_w2f)[u32idx * 2 + half] = __float2bfloat16(lo);
}

// ---------------- degree ----------------
__global__ void deg_kernel(const int* __restrict__ dst, int E) {
    int i = blockIdx.x * blockDim.x + threadIdx.x;
    if (i < E) atomicAdd(&g_deg[dst[i]], 1);
}
// inv + layer-0 W split
__global__ void inv_kernel(const float* __restrict__ W0, int d0, int N) {
    int i = blockIdx.x * blockDim.x + threadIdx.x;
    if (i < N) g_inv[i] = 1.f / (float)(g_deg[i] + 1);
    if (blockIdx.x < 64) wsplit_one(W0, d0, blockIdx.x * 256 + threadIdx.x);
}

// ---------------- mma.sync bf16 helper ----------------
__device__ __forceinline__ void mma_bf16(float4& d, const uint32_t* a, const uint32_t* b) {
    asm volatile(
        "mma.sync.aligned.m16n8k16.row.col.f32.bf16.bf16.f32 "
        "{%0,%1,%2,%3}, {%4,%5,%6,%7}, {%8,%9}, {%0,%1,%2,%3};"
        : "+f"(d.x), "+f"(d.y), "+f"(d.z), "+f"(d.w)
        : "r"(a[0]), "r"(a[1]), "r"(a[2]), "r"(a[3]), "r"(b[0]), "r"(b[1]));
}

static constexpr int ROWB = 144;   // A smem row stride (bytes)
static constexpr int XST  = 68;    // xs/selfplane row stride (floats)

// ---------------- fused GEMM kernel: tile = 32 nodes x 256 cols ----------------
__global__ __launch_bounds__(256, 3)
void mma_kernel(const float* __restrict__ x, const float* __restrict__ U,
                const float* __restrict__ cvec, int d, int useBN, int N) {
    __shared__ __align__(16) char  sA1[32 * ROWB];
    __shared__ __align__(16) char  sA2[32 * ROWB];
    __shared__ __align__(16) float xs[32 * XST];   // fp32 x' ; reused as selfplane

    int tid  = threadIdx.x;
    int base = blockIdx.x * 32;

    // ---- load x' (BN-folded) into xs ----
    int c4n = d >> 2;
    int cnt = 32 * c4n;
    for (int f = tid; f < cnt; f += 256) {
        int row = f / c4n, c4 = f - row * c4n;
        float4 v = make_float4(0.f, 0.f, 0.f, 0.f);
        if (base + row < N) v = *(const float4*)(x + (size_t)base * d + (size_t)f * 4);
        if (useBN) {
            int c = c4 * 4;
            v.x = v.x * g_s[c]     + g_t[c];
            v.y = v.y * g_s[c + 1] + g_t[c + 1];
            v.z = v.z * g_s[c + 2] + g_t[c + 2];
            v.w = v.w * g_s[c + 3] + g_t[c + 3];
        }
        *(float4*)(xs + row * XST + c4 * 4) = v;
    }
    if (d == 32) {  // zero upper K half
        int row = tid >> 3, c = 32 + (tid & 7) * 4;
        *(float4*)(xs + row * XST + c) = make_float4(0.f, 0.f, 0.f, 0.f);
    }
    __syncthreads();

    // ---- bf16 split of A into smem ----
    {
        int row = tid >> 3, cg = tid & 7;
        float4 v0 = *(float4*)(xs + row * XST + cg * 8);
        float4 v1 = *(float4*)(xs + row * XST + cg * 8 + 4);
        float vv[8] = {v0.x, v0.y, v0.z, v0.w, v1.x, v1.y, v1.z, v1.w};
        uint32_t hiw[4], low[4];
#pragma unroll
        for (int j = 0; j < 4; j++) {
            __nv_bfloat16 h0 = __float2bfloat16(vv[j * 2]);
            __nv_bfloat16 h1 = __float2bfloat16(vv[j * 2 + 1]);
            __nv_bfloat16 l0 = __float2bfloat16(vv[j * 2]     - __bfloat162float(h0));
            __nv_bfloat16 l1 = __float2bfloat16(vv[j * 2 + 1] - __bfloat162float(h1));
            hiw[j] = (uint32_t)*(uint16_t*)&h0 | ((uint32_t)*(uint16_t*)&h1 << 16);
            low[j] = (uint32_t)*(uint16_t*)&l0 | ((uint32_t)*(uint16_t*)&l1 << 16);
        }
        *(uint4*)(sA1 + row * ROWB + cg * 16) = make_uint4(hiw[0], hiw[1], hiw[2], hiw[3]);
        *(uint4*)(sA2 + row * ROWB + cg * 16) = make_uint4(low[0], low[1], low[2], low[3]);
    }

    // ---- xu = x' @ U (warp w: rows w*4..w*4+4) ----
    {
        int w = tid >> 5, lane = tid & 31;
        float4 u0 = __ldg((const float4*)(U + lane * 4));
        float4 u1 = make_float4(0.f, 0.f, 0.f, 0.f);
        if (d == 64) u1 = __ldg((const float4*)(U + (lane + 32) * 4));
#pragma unroll
        for (int t2 = 0; t2 < 4; t2++) {
            int rloc = w * 4 + t2;
            float v0 = xs[rloc * XST + lane];
            float v1 = xs[rloc * XST + 32 + lane];  // zero when d==32
            float4 p;
            p.x = v0 * u0.x + v1 * u1.x;
            p.y = v0 * u0.y + v1 * u1.y;
            p.z = v0 * u0.z + v1 * u1.z;
            p.w = v0 * u0.w + v1 * u1.w;
#pragma unroll
            for (int off = 16; off >= 1; off >>= 1) {
                p.x += __shfl_xor_sync(0xffffffffu, p.x, off);
                p.y += __shfl_xor_sync(0xffffffffu, p.y, off);
                p.z += __shfl_xor_sync(0xffffffffu, p.z, off);
                p.w += __shfl_xor_sync(0xffffffffu, p.w, off);
            }
            if (lane == 0 && base + rloc < N)
                *(float4*)(g_xu + (size_t)(base + rloc) * 4) = p;
        }
    }
    __syncthreads();

    // ---- MMA mainloop ----
    int w = tid >> 5, lane = tid & 31;
    int g = lane >> 2, tg = lane & 3;
    int q = w & 3, r = w >> 2;
    int rblk = r * 16;

    float4 acc[8];
#pragma unroll
    for (int i = 0; i < 8; i++) acc[i] = make_float4(0.f, 0.f, 0.f, 0.f);

#pragma unroll
    for (int kk = 0; kk < 4; kk++) {
        int k0 = kk * 16;
        int ro0 = (rblk + g) * ROWB, ro1 = (rblk + g + 8) * ROWB;
        int kc0 = (k0 + tg * 2) * 2, kc1 = (k0 + 8 + tg * 2) * 2;
        uint32_t a1f[4], a2f[4];
        a1f[0] = *(const uint32_t*)(sA1 + ro0 + kc0);
        a1f[1] = *(const uint32_t*)(sA1 + ro1 + kc0);
        a1f[2] = *(const uint32_t*)(sA1 + ro0 + kc1);
        a1f[3] = *(const uint32_t*)(sA1 + ro1 + kc1);
        a2f[0] = *(const uint32_t*)(sA2 + ro0 + kc0);
        a2f[1] = *(const uint32_t*)(sA2 + ro1 + kc0);
        a2f[2] = *(const uint32_t*)(sA2 + ro0 + kc1);
        a2f[3] = *(const uint32_t*)(sA2 + ro1 + kc1);
#pragma unroll
        for (int nt = 0; nt < 8; nt++) {
            int fidx = (((q * 8 + nt) * 4) + kk) * 32 + lane;
            uint2 B1 = __ldg((const uint2*)g_w1f + fidx);
            uint2 B2 = __ldg((const uint2*)g_w2f + fidx);
            uint32_t b1[2] = {B1.x, B1.y};
            uint32_t b2[2] = {B2.x, B2.y};
            mma_bf16(acc[nt], a1f, b1);
            mma_bf16(acc[nt], a2f, b1);
            mma_bf16(acc[nt], a1f, b2);
        }
    }

    // ---- write xw (fp16) ----
    int row0 = base + rblk + g;
    int row1 = row0 + 8;
#pragma unroll
    for (int nt = 0; nt < 8; nt++) {
        int col = q * 64 + nt * 8 + tg * 2;
        if (row0 < N)
            *(__half2*)(g_xwh + (size_t)row0 * 256 + col) = __floats2half2_rn(acc[nt].x, acc[nt].y);
        if (row1 < N)
            *(__half2*)(g_xwh + (size_t)row1 * 256 + col) = __floats2half2_rn(acc[nt].z, acc[nt].w);
    }

    // ---- self-loop message -> g_agg init (fp32, exact) ----
    float c0 = __ldg(cvec + 0), c1 = __ldg(cvec + 1);
    float c2 = __ldg(cvec + 2), c3 = __ldg(cvec + 3);
    float mx = fmaxf(fmaxf(c0, c1), fmaxf(c2, c3));
    float e0 = __expf(c0 - mx), e1 = __expf(c1 - mx);
    float e2 = __expf(c2 - mx), e3 = __expf(c3 - mx);
    float sinv = 1.f / (e0 + e1 + e2 + e3);
    float aq = (q == 0 ? e0 : q == 1 ? e1 : q == 2 ? e2 : e3) * sinv;

    __syncthreads();  // xs dead -> reuse as selfplane [32][XST]
    {
        int rw = tid >> 3, c = (tid & 7) * 8;
        *(float4*)(xs + rw * XST + c)     = make_float4(0.f, 0.f, 0.f, 0.f);
        *(float4*)(xs + rw * XST + c + 4) = make_float4(0.f, 0.f, 0.f, 0.f);
    }
    __syncthreads();
#pragma unroll
    for (int qq = 0; qq < 4; qq++) {
        if (q == qq) {
#pragma unroll
            for (int nt = 0; nt < 8; nt++) {
                int cl = nt * 8 + tg * 2;
                float2* p0 = (float2*)(xs + (rblk + g) * XST + cl);
                float2* p1 = (float2*)(xs + (rblk + g + 8) * XST + cl);
                float2 v0 = *p0, v1 = *p1;
                v0.x += aq * acc[nt].x; v0.y += aq * acc[nt].y;
                v1.x += aq * acc[nt].z; v1.y += aq * acc[nt].w;
                *p0 = v0; *p1 = v1;
            }
        }
        __syncthreads();
    }
    {
        int rw = tid >> 3, c = (tid & 7) * 8;
        if (base + rw < N) {
            *(float4*)(g_agg + (size_t)(base + rw) * 64 + c)     = *(float4*)(xs + rw * XST + c);
            *(float4*)(g_agg + (size_t)(base + rw) * 64 + c + 4) = *(float4*)(xs + rw * XST + c + 4);
        }
    }
}

// ---------------- edge kernel v3: 16 lanes/edge, lane0 softmax + shfl broadcast ----------------
__global__ void edge_kernel(const int* __restrict__ src, const int* __restrict__ dst,
                            const float* __restrict__ cvec, int E) {
    int tid  = blockIdx.x * blockDim.x + threadIdx.x;
    int gw   = tid >> 5;
    int lane = threadIdx.x & 31;
    int sub  = lane >> 4;   // edge slot within warp (0..1)
    int j    = lane & 15;   // channel group (4 channels)
    int e = gw * 2 + sub;

    int s = 0, dv = 0;
    float a0 = 0.f, a1 = 0.f, a2 = 0.f, a3 = 0.f;
    if (j == 0 && e < E) {
        s  = __ldg(src + e);
        dv = __ldg(dst + e);
        const float4 us = *(const float4*)(g_xu + s  * 4);
        const float4 ud = *(const float4*)(g_xu + dv * 4);
        float l0 = ud.x - us.x + __ldg(cvec + 0);
        float l1 = ud.y - us.y + __ldg(cvec + 1);
        float l2 = ud.z - us.z + __ldg(cvec + 2);
        float l3 = ud.w - us.w + __ldg(cvec + 3);
        float mx = fmaxf(fmaxf(l0, l1), fmaxf(l2, l3));
        float e0 = __expf(l0 - mx), e1 = __expf(l1 - mx);
        float e2 = __expf(l2 - mx), e3 = __expf(l3 - mx);
        float inv = 1.f / (e0 + e1 + e2 + e3);
        a0 = e0 * inv; a1 = e1 * inv; a2 = e2 * inv; a3 = e3 * inv;
    }
    int bl = sub * 16;  // broadcast source lane
    s  = __shfl_sync(0xffffffffu, s,  bl);
    dv = __shfl_sync(0xffffffffu, dv, bl);
    a0 = __shfl_sync(0xffffffffu, a0, bl);
    a1 = __shfl_sync(0xffffffffu, a1, bl);
    a2 = __shfl_sync(0xffffffffu, a2, bl);
    a3 = __shfl_sync(0xffffffffu, a3, bl);
    if (e >= E) return;

    // lane j owns channels [j*4, j*4+4): one uint2 (4 halfs) per head
    const uint2* xwp = (const uint2*)(g_xwh + (size_t)s * 256);
    uint2 u0 = __ldg(xwp + j);          // head 0 (row = 64 uint2; head h at h*16)
    uint2 u1 = __ldg(xwp + 16 + j);     // head 1
    uint2 u2 = __ldg(xwp + 32 + j);     // head 2
    uint2 u3 = __ldg(xwp + 48 + j);     // head 3

    float2 f0a = __half22float2(*(const __half2*)&u0.x), f0b = __half22float2(*(const __half2*)&u0.y);
    float2 f1a = __half22float2(*(const __half2*)&u1.x), f1b = __half22float2(*(const __half2*)&u1.y);
    float2 f2a = __half22float2(*(const __half2*)&u2.x), f2b = __half22float2(*(const __half2*)&u2.y);
    float2 f3a = __half22float2(*(const __half2*)&u3.x), f3b = __half22float2(*(const __half2*)&u3.y);

    float4 m;
    m.x = a0 * f0a.x + a1 * f1a.x + a2 * f2a.x + a3 * f3a.x;
    m.y = a0 * f0a.y + a1 * f1a.y + a2 * f2a.y + a3 * f3a.y;
    m.z = a0 * f0b.x + a1 * f1b.x + a2 * f2b.x + a3 * f3b.x;
    m.w = a0 * f0b.y + a1 * f1b.y + a2 * f2b.y + a3 * f3b.y;

    atomicAdd((float4*)(g_agg + (size_t)dv * 64 + j * 4), m);
}

// ---------------- finalize: mean + bias (+relu + BN stats + s/t fold + next W split) ----------------
__global__ void finalize_kernel(const float* __restrict__ b, const float* __restrict__ gvec,
                                const float* __restrict__ bevec, const float* __restrict__ Wnext,
                                float* __restrict__ out, int N, int doStats) {
    if (doStats && blockIdx.x < 64)
        wsplit_one(Wnext, 64, blockIdx.x * 256 + threadIdx.x);

    int c = threadIdx.x & 63;
    int r = threadIdx.x >> 6;
    float bc = __ldg(b + c);
    float ls = 0.f, lq = 0.f;
    int base = blockIdx.x * 64;

#pragma unroll
    for (int j = 0; j < 16; j++) {
        int i = base + r + j * 4;
        if (i >= N) break;
        float v = g_agg[(size_t)i * 64 + c] * g_inv[i] + bc;
        if (doStats) {
            v = fmaxf(v, 0.f);
            out[(size_t)i * 64 + c] = v;
            ls += v;
            lq += v * v;
        } else {
            out[(size_t)i * 64 + c] = v;
        }
    }

    if (doStats) {
        __shared__ double ss[256], sq[256];
        __shared__ int isLast;
        ss[threadIdx.x] = (double)ls; sq[threadIdx.x] = (double)lq;
        __syncthreads();
        if (threadIdx.x < 128) {
            ss[threadIdx.x] += ss[threadIdx.x + 128];
            sq[threadIdx.x] += sq[threadIdx.x + 128];
        }
        __syncthreads();
        if (threadIdx.x < 64) {
            atomicAdd(&g_stats[c],      ss[threadIdx.x] + ss[threadIdx.x + 64]);
            atomicAdd(&g_stats[64 + c], sq[threadIdx.x] + sq[threadIdx.x + 64]);
        }
        __syncthreads();
        if (threadIdx.x == 0) {
            __threadfence();
            unsigned v = atomicAdd(&g_fincnt, 1u);
            isLast = (v == gridDim.x - 1) ? 1 : 0;
        }
        __syncthreads();
        if (isLast) {
            if (threadIdx.x < 64) {
                __threadfence();
                int cc = threadIdx.x;
                double mean = g_stats[cc] / (double)N;
                double var  = g_stats[64 + cc] / (double)N - mean * mean;
                float s = __ldg(gvec + cc) * rsqrtf((float)var + 1e-5f);
                g_s[cc] = s;
                g_t[cc] = __ldg(bevec + cc) - (float)mean * s;
                g_stats[cc] = 0.0;
                g_stats[64 + cc] = 0.0;
            }
            if (threadIdx.x == 0) g_fincnt = 0u;
        }
    }
}

// ---------------- launch ----------------
extern "C" void kernel_launch(void* const* d_in, const int* in_sizes, int n_in,
                              void* d_out, int out_size) {
    const float* x  = (const float*)d_in[0];
    const int*   ei = (const int*)d_in[1];
    const float* W [3] = {(const float*)d_in[2],  (const float*)d_in[6],  (const float*)d_in[10]};
    const float* U [3] = {(const float*)d_in[3],  (const float*)d_in[7],  (const float*)d_in[11]};
    const float* Cv[3] = {(const float*)d_in[4],  (const float*)d_in[8],  (const float*)d_in[12]};
    const float* B [3] = {(const float*)d_in[5],  (const float*)d_in[9],  (const float*)d_in[13]};
    const float* G [2] = {(const float*)d_in[14], (const float*)d_in[16]};
    const float* BE[2] = {(const float*)d_in[15], (const float*)d_in[17]};

    int N = in_sizes[0] / 32;
    int E = in_sizes[1] / 2;
    const int* src = ei;
    const int* dst = ei + E;

    void *p_deg = nullptr, *p_h = nullptr;
    cudaGetSymbolAddress(&p_deg, g_deg);
    cudaGetSymbolAddress(&p_h,   g_h);
    float* hbuf = (float*)p_h;

    cudaMemsetAsync(p_deg, 0, (size_t)N * sizeof(int));
    deg_kernel<<<(E + 255) / 256, 256>>>(dst, E);
    inv_kernel<<<(N + 255) / 256, 256>>>(W[0], 32, N);   // also splits W0

    int mma_blocks  = (N + 31) / 32;
    int edge_blocks = ((size_t)E * 16 + 255) / 256;
    int fin_blocks  = (N + 63) / 64;

    for (int l = 0; l < 3; l++) {
        const float* xin = (l == 0) ? x : hbuf;
        int d = (l == 0) ? 32 : 64;
        mma_kernel<<<mma_blocks, 256>>>(xin, U[l], Cv[l], d, (l > 0) ? 1 : 0, N);
        edge_kernel<<<edge_blocks, 256>>>(src, dst, Cv[l], E);
        if (l < 2) {
            finalize_kernel<<<fin_blocks, 256>>>(B[l], G[l], BE[l], W[l + 1], hbuf, N, 1);
        } else {
            finalize_kernel<<<fin_blocks, 256>>>(B[l], nullptr, nullptr, nullptr, (float*)d_out, N, 0);
        }
    }
}

// round 12
// speedup vs baseline: 1.0290x; 1.0146x over previous
#include <cuda_runtime.h>
#include <cuda_bf16.h>
#include <cuda_fp16.h>
#include <cstdint>

#define MAXN 25000
#define MAXE 200000

// ---------------- device scratch ----------------
__device__ __align__(16) __half   g_xwh[MAXN * 256];  // per-node linear output, fp16 (edge-only consumer)
__device__ __align__(16) float    g_xu[MAXN * 4];     // per-node u-projection
__device__ __align__(16) float    g_att[MAXE * 4];    // per-edge softmax attention
__device__ __align__(16) float    g_h [MAXN * 64];    // hidden features
__device__ __align__(16) float    g_agg[MAXN * 64];   // scatter accumulator
__device__ __align__(16) uint32_t g_w1f[8192];        // W split hi, fragment-major
__device__ __align__(16) uint32_t g_w2f[8192];        // W split lo, fragment-major
__device__ int      g_deg[MAXN];
__device__ float    g_inv[MAXN];
__device__ double   g_stats[128];   // zero-init; reset by finalize last-block
__device__ unsigned g_fincnt;       // zero-init; reset by finalize last-block
__device__ float    g_s[64];
__device__ float    g_t[64];

// ---------------- W split into fragment-major layout ----------------
__device__ __forceinline__ void wsplit_one(const float* __restrict__ W, int d, int idx) {
    int n = idx >> 6, k = idx & 63;
    float v = (k < d) ? __ldg(W + k * 256 + n) : 0.f;
    __nv_bfloat16 hi = __float2bfloat16(v);
    float lo = v - __bfloat162float(hi);
    int kk = k >> 4, rem = k & 15;
    int word = rem >> 3, r2 = rem & 7, tg = r2 >> 1, half = r2 & 1;
    int u32idx = ((((n >> 3) * 4) + kk) * 32 + (n & 7) * 4 + tg) * 2 + word;
    ((__nv_bfloat16*)g_w1f)[u32idx * 2 + half] = hi;
    ((__nv_bfloat16*)g_w2f)[u32idx * 2 + half] = __float2bfloat16(lo);
}

// ---------------- degree ----------------
__global__ void deg_kernel(const int* __restrict__ dst, int E) {
    int i = blockIdx.x * blockDim.x + threadIdx.x;
    if (i < E) atomicAdd(&g_deg[dst[i]], 1);
}
// inv + layer-0 W split
__global__ void inv_kernel(const float* __restrict__ W0, int d0, int N) {
    int i = blockIdx.x * blockDim.x + threadIdx.x;
    if (i < N) g_inv[i] = 1.f / (float)(g_deg[i] + 1);
    if (blockIdx.x < 64) wsplit_one(W0, d0, blockIdx.x * 256 + threadIdx.x);
}

// ---------------- mma.sync bf16 helper ----------------
__device__ __forceinline__ void mma_bf16(float4& d, const uint32_t* a, const uint32_t* b) {
    asm volatile(
        "mma.sync.aligned.m16n8k16.row.col.f32.bf16.bf16.f32 "
        "{%0,%1,%2,%3}, {%4,%5,%6,%7}, {%8,%9}, {%0,%1,%2,%3};"
        : "+f"(d.x), "+f"(d.y), "+f"(d.z), "+f"(d.w)
        : "r"(a[0]), "r"(a[1]), "r"(a[2]), "r"(a[3]), "r"(b[0]), "r"(b[1]));
}

static constexpr int ROWB = 144;   // A smem row stride (bytes)
static constexpr int XST  = 68;    // xs/selfplane row stride (floats)

// ---------------- fused GEMM kernel: tile = 32 nodes x 256 cols ----------------
__global__ __launch_bounds__(256, 3)
void mma_kernel(const float* __restrict__ x, const float* __restrict__ U,
                const float* __restrict__ cvec, int d, int useBN, int N) {
    __shared__ __align__(16) char  sA1[32 * ROWB];
    __shared__ __align__(16) char  sA2[32 * ROWB];
    __shared__ __align__(16) float xs[32 * XST];   // fp32 x' ; reused as selfplane

    int tid  = threadIdx.x;
    int base = blockIdx.x * 32;

    // ---- load x' (BN-folded) into xs ----
    int c4n = d >> 2;
    int cnt = 32 * c4n;
    for (int f = tid; f < cnt; f += 256) {
        int row = f / c4n, c4 = f - row * c4n;
        float4 v = make_float4(0.f, 0.f, 0.f, 0.f);
        if (base + row < N) v = *(const float4*)(x + (size_t)base * d + (size_t)f * 4);
        if (useBN) {
            int c = c4 * 4;
            v.x = v.x * g_s[c]     + g_t[c];
            v.y = v.y * g_s[c + 1] + g_t[c + 1];
            v.z = v.z * g_s[c + 2] + g_t[c + 2];
            v.w = v.w * g_s[c + 3] + g_t[c + 3];
        }
        *(float4*)(xs + row * XST + c4 * 4) = v;
    }
    if (d == 32) {  // zero upper K half
        int row = tid >> 3, c = 32 + (tid & 7) * 4;
        *(float4*)(xs + row * XST + c) = make_float4(0.f, 0.f, 0.f, 0.f);
    }
    __syncthreads();

    // ---- bf16 split of A into smem ----
    {
        int row = tid >> 3, cg = tid & 7;
        float4 v0 = *(float4*)(xs + row * XST + cg * 8);
        float4 v1 = *(float4*)(xs + row * XST + cg * 8 + 4);
        float vv[8] = {v0.x, v0.y, v0.z, v0.w, v1.x, v1.y, v1.z, v1.w};
        uint32_t hiw[4], low[4];
#pragma unroll
        for (int j = 0; j < 4; j++) {
            __nv_bfloat16 h0 = __float2bfloat16(vv[j * 2]);
            __nv_bfloat16 h1 = __float2bfloat16(vv[j * 2 + 1]);
            __nv_bfloat16 l0 = __float2bfloat16(vv[j * 2]     - __bfloat162float(h0));
            __nv_bfloat16 l1 = __float2bfloat16(vv[j * 2 + 1] - __bfloat162float(h1));
            hiw[j] = (uint32_t)*(uint16_t*)&h0 | ((uint32_t)*(uint16_t*)&h1 << 16);
            low[j] = (uint32_t)*(uint16_t*)&l0 | ((uint32_t)*(uint16_t*)&l1 << 16);
        }
        *(uint4*)(sA1 + row * ROWB + cg * 16) = make_uint4(hiw[0], hiw[1], hiw[2], hiw[3]);
        *(uint4*)(sA2 + row * ROWB + cg * 16) = make_uint4(low[0], low[1], low[2], low[3]);
    }

    // ---- xu = x' @ U (warp w: rows w*4..w*4+4) ----
    {
        int w = tid >> 5, lane = tid & 31;
        float4 u0 = __ldg((const float4*)(U + lane * 4));
        float4 u1 = make_float4(0.f, 0.f, 0.f, 0.f);
        if (d == 64) u1 = __ldg((const float4*)(U + (lane + 32) * 4));
#pragma unroll
        for (int t2 = 0; t2 < 4; t2++) {
            int rloc = w * 4 + t2;
            float v0 = xs[rloc * XST + lane];
            float v1 = xs[rloc * XST + 32 + lane];  // zero when d==32
            float4 p;
            p.x = v0 * u0.x + v1 * u1.x;
            p.y = v0 * u0.y + v1 * u1.y;
            p.z = v0 * u0.z + v1 * u1.z;
            p.w = v0 * u0.w + v1 * u1.w;
#pragma unroll
            for (int off = 16; off >= 1; off >>= 1) {
                p.x += __shfl_xor_sync(0xffffffffu, p.x, off);
                p.y += __shfl_xor_sync(0xffffffffu, p.y, off);
                p.z += __shfl_xor_sync(0xffffffffu, p.z, off);
                p.w += __shfl_xor_sync(0xffffffffu, p.w, off);
            }
            if (lane == 0 && base + rloc < N)
                *(float4*)(g_xu + (size_t)(base + rloc) * 4) = p;
        }
    }
    __syncthreads();

    // ---- MMA mainloop ----
    int w = tid >> 5, lane = tid & 31;
    int g = lane >> 2, tg = lane & 3;
    int q = w & 3, r = w >> 2;
    int rblk = r * 16;

    float4 acc[8];
#pragma unroll
    for (int i = 0; i < 8; i++) acc[i] = make_float4(0.f, 0.f, 0.f, 0.f);

#pragma unroll
    for (int kk = 0; kk < 4; kk++) {
        int k0 = kk * 16;
        int ro0 = (rblk + g) * ROWB, ro1 = (rblk + g + 8) * ROWB;
        int kc0 = (k0 + tg * 2) * 2, kc1 = (k0 + 8 + tg * 2) * 2;
        uint32_t a1f[4], a2f[4];
        a1f[0] = *(const uint32_t*)(sA1 + ro0 + kc0);
        a1f[1] = *(const uint32_t*)(sA1 + ro1 + kc0);
        a1f[2] = *(const uint32_t*)(sA1 + ro0 + kc1);
        a1f[3] = *(const uint32_t*)(sA1 + ro1 + kc1);
        a2f[0] = *(const uint32_t*)(sA2 + ro0 + kc0);
        a2f[1] = *(const uint32_t*)(sA2 + ro1 + kc0);
        a2f[2] = *(const uint32_t*)(sA2 + ro0 + kc1);
        a2f[3] = *(const uint32_t*)(sA2 + ro1 + kc1);
#pragma unroll
        for (int nt = 0; nt < 8; nt++) {
            int fidx = (((q * 8 + nt) * 4) + kk) * 32 + lane;
            uint2 B1 = __ldg((const uint2*)g_w1f + fidx);
            uint2 B2 = __ldg((const uint2*)g_w2f + fidx);
            uint32_t b1[2] = {B1.x, B1.y};
            uint32_t b2[2] = {B2.x, B2.y};
            mma_bf16(acc[nt], a1f, b1);
            mma_bf16(acc[nt], a2f, b1);
            mma_bf16(acc[nt], a1f, b2);
        }
    }

    // ---- write xw (fp16) ----
    int row0 = base + rblk + g;
    int row1 = row0 + 8;
#pragma unroll
    for (int nt = 0; nt < 8; nt++) {
        int col = q * 64 + nt * 8 + tg * 2;
        if (row0 < N)
            *(__half2*)(g_xwh + (size_t)row0 * 256 + col) = __floats2half2_rn(acc[nt].x, acc[nt].y);
        if (row1 < N)
            *(__half2*)(g_xwh + (size_t)row1 * 256 + col) = __floats2half2_rn(acc[nt].z, acc[nt].w);
    }

    // ---- self-loop message -> g_agg init (fp32, exact) ----
    float c0 = __ldg(cvec + 0), c1 = __ldg(cvec + 1);
    float c2 = __ldg(cvec + 2), c3 = __ldg(cvec + 3);
    float mx = fmaxf(fmaxf(c0, c1), fmaxf(c2, c3));
    float e0 = __expf(c0 - mx), e1 = __expf(c1 - mx);
    float e2 = __expf(c2 - mx), e3 = __expf(c3 - mx);
    float sinv = 1.f / (e0 + e1 + e2 + e3);
    float aq = (q == 0 ? e0 : q == 1 ? e1 : q == 2 ? e2 : e3) * sinv;

    __syncthreads();  // xs dead -> reuse as selfplane [32][XST]
    {
        int rw = tid >> 3, c = (tid & 7) * 8;
        *(float4*)(xs + rw * XST + c)     = make_float4(0.f, 0.f, 0.f, 0.f);
        *(float4*)(xs + rw * XST + c + 4) = make_float4(0.f, 0.f, 0.f, 0.f);
    }
    __syncthreads();
#pragma unroll
    for (int qq = 0; qq < 4; qq++) {
        if (q == qq) {
#pragma unroll
            for (int nt = 0; nt < 8; nt++) {
                int cl = nt * 8 + tg * 2;
                float2* p0 = (float2*)(xs + (rblk + g) * XST + cl);
                float2* p1 = (float2*)(xs + (rblk + g + 8) * XST + cl);
                float2 v0 = *p0, v1 = *p1;
                v0.x += aq * acc[nt].x; v0.y += aq * acc[nt].y;
                v1.x += aq * acc[nt].z; v1.y += aq * acc[nt].w;
                *p0 = v0; *p1 = v1;
            }
        }
        __syncthreads();
    }
    {
        int rw = tid >> 3, c = (tid & 7) * 8;
        if (base + rw < N) {
            *(float4*)(g_agg + (size_t)(base + rw) * 64 + c)     = *(float4*)(xs + rw * XST + c);
            *(float4*)(g_agg + (size_t)(base + rw) * 64 + c + 4) = *(float4*)(xs + rw * XST + c + 4);
        }
    }
}

// ---------------- att kernel: per-edge softmax over heads ----------------
__global__ void att_kernel(const int* __restrict__ src, const int* __restrict__ dst,
                           const float* __restrict__ cvec, int E) {
    int e = blockIdx.x * blockDim.x + threadIdx.x;
    if (e >= E) return;
    int s  = __ldg(src + e);
    int dv = __ldg(dst + e);
    const float4 us = *(const float4*)(g_xu + s  * 4);
    const float4 ud = *(const float4*)(g_xu + dv * 4);
    float l0 = ud.x - us.x + __ldg(cvec + 0);
    float l1 = ud.y - us.y + __ldg(cvec + 1);
    float l2 = ud.z - us.z + __ldg(cvec + 2);
    float l3 = ud.w - us.w + __ldg(cvec + 3);
    float mx = fmaxf(fmaxf(l0, l1), fmaxf(l2, l3));
    float e0 = __expf(l0 - mx), e1 = __expf(l1 - mx);
    float e2 = __expf(l2 - mx), e3 = __expf(l3 - mx);
    float inv = 1.f / (e0 + e1 + e2 + e3);
    *(float4*)(g_att + (size_t)e * 4) = make_float4(e0 * inv, e1 * inv, e2 * inv, e3 * inv);
}

// ---------------- edge kernel: 16 lanes/edge, precomputed attention ----------------
__global__ void edge_kernel(const int* __restrict__ src, const int* __restrict__ dst, int E) {
    int tid = blockIdx.x * blockDim.x + threadIdx.x;
    int e = tid >> 4;
    int j = tid & 15;
    if (e >= E) return;
    int s  = __ldg(src + e);
    int dv = __ldg(dst + e);
    float4 a = __ldg((const float4*)(g_att + (size_t)e * 4));

    // lane j owns channels [j*4, j*4+4): one uint2 (4 halfs) per head
    const uint2* xwp = (const uint2*)(g_xwh + (size_t)s * 256);
    uint2 u0 = __ldg(xwp + j);          // head 0
    uint2 u1 = __ldg(xwp + 16 + j);     // head 1
    uint2 u2 = __ldg(xwp + 32 + j);     // head 2
    uint2 u3 = __ldg(xwp + 48 + j);     // head 3

    float2 f0a = __half22float2(*(const __half2*)&u0.x), f0b = __half22float2(*(const __half2*)&u0.y);
    float2 f1a = __half22float2(*(const __half2*)&u1.x), f1b = __half22float2(*(const __half2*)&u1.y);
    float2 f2a = __half22float2(*(const __half2*)&u2.x), f2b = __half22float2(*(const __half2*)&u2.y);
    float2 f3a = __half22float2(*(const __half2*)&u3.x), f3b = __half22float2(*(const __half2*)&u3.y);

    float4 m;
    m.x = a.x * f0a.x + a.y * f1a.x + a.z * f2a.x + a.w * f3a.x;
    m.y = a.x * f0a.y + a.y * f1a.y + a.z * f2a.y + a.w * f3a.y;
    m.z = a.x * f0b.x + a.y * f1b.x + a.z * f2b.x + a.w * f3b.x;
    m.w = a.x * f0b.y + a.y * f1b.y + a.z * f2b.y + a.w * f3b.y;

    atomicAdd((float4*)(g_agg + (size_t)dv * 64 + j * 4), m);
}

// ---------------- finalize: mean + bias (+relu + BN stats + s/t fold + next W split) ----------------
__global__ void finalize_kernel(const float* __restrict__ b, const float* __restrict__ gvec,
                                const float* __restrict__ bevec, const float* __restrict__ Wnext,
                                float* __restrict__ out, int N, int doStats) {
    if (doStats && blockIdx.x < 64)
        wsplit_one(Wnext, 64, blockIdx.x * 256 + threadIdx.x);

    int c = threadIdx.x & 63;
    int r = threadIdx.x >> 6;
    float bc = __ldg(b + c);
    float ls = 0.f, lq = 0.f;
    int base = blockIdx.x * 64;

#pragma unroll
    for (int j = 0; j < 16; j++) {
        int i = base + r + j * 4;
        if (i >= N) break;
        float v = g_agg[(size_t)i * 64 + c] * g_inv[i] + bc;
        if (doStats) {
            v = fmaxf(v, 0.f);
            out[(size_t)i * 64 + c] = v;
            ls += v;
            lq += v * v;
        } else {
            out[(size_t)i * 64 + c] = v;
        }
    }

    if (doStats) {
        __shared__ double ss[256], sq[256];
        __shared__ int isLast;
        ss[threadIdx.x] = (double)ls; sq[threadIdx.x] = (double)lq;
        __syncthreads();
        if (threadIdx.x < 128) {
            ss[threadIdx.x] += ss[threadIdx.x + 128];
            sq[threadIdx.x] += sq[threadIdx.x + 128];
        }
        __syncthreads();
        if (threadIdx.x < 64) {
            atomicAdd(&g_stats[c],      ss[threadIdx.x] + ss[threadIdx.x + 64]);
            atomicAdd(&g_stats[64 + c], sq[threadIdx.x] + sq[threadIdx.x + 64]);
        }
        __syncthreads();
        if (threadIdx.x == 0) {
            __threadfence();
            unsigned v = atomicAdd(&g_fincnt, 1u);
            isLast = (v == gridDim.x - 1) ? 1 : 0;
        }
        __syncthreads();
        if (isLast) {
            if (threadIdx.x < 64) {
                __threadfence();
                int cc = threadIdx.x;
                double mean = g_stats[cc] / (double)N;
                double var  = g_stats[64 + cc] / (double)N - mean * mean;
                float s = __ldg(gvec + cc) * rsqrtf((float)var + 1e-5f);
                g_s[cc] = s;
                g_t[cc] = __ldg(bevec + cc) - (float)mean * s;
                g_stats[cc] = 0.0;
                g_stats[64 + cc] = 0.0;
            }
            if (threadIdx.x == 0) g_fincnt = 0u;
        }
    }
}

// ---------------- launch ----------------
extern "C" void kernel_launch(void* const* d_in, const int* in_sizes, int n_in,
                              void* d_out, int out_size) {
    const float* x  = (const float*)d_in[0];
    const int*   ei = (const int*)d_in[1];
    const float* W [3] = {(const float*)d_in[2],  (const float*)d_in[6],  (const float*)d_in[10]};
    const float* U [3] = {(const float*)d_in[3],  (const float*)d_in[7],  (const float*)d_in[11]};
    const float* Cv[3] = {(const float*)d_in[4],  (const float*)d_in[8],  (const float*)d_in[12]};
    const float* B [3] = {(const float*)d_in[5],  (const float*)d_in[9],  (const float*)d_in[13]};
    const float* G [2] = {(const float*)d_in[14], (const float*)d_in[16]};
    const float* BE[2] = {(const float*)d_in[15], (const float*)d_in[17]};

    int N = in_sizes[0] / 32;
    int E = in_sizes[1] / 2;
    const int* src = ei;
    const int* dst = ei + E;

    void *p_deg = nullptr, *p_h = nullptr;
    cudaGetSymbolAddress(&p_deg, g_deg);
    cudaGetSymbolAddress(&p_h,   g_h);
    float* hbuf = (float*)p_h;

    cudaMemsetAsync(p_deg, 0, (size_t)N * sizeof(int));
    deg_kernel<<<(E + 255) / 256, 256>>>(dst, E);
    inv_kernel<<<(N + 255) / 256, 256>>>(W[0], 32, N);   // also splits W0

    int mma_blocks  = (N + 31) / 32;
    int att_blocks  = (E + 255) / 256;
    int edge_blocks = ((size_t)E * 16 + 255) / 256;
    int fin_blocks  = (N + 63) / 64;

    for (int l = 0; l < 3; l++) {
        const float* xin = (l == 0) ? x : hbuf;
        int d = (l == 0) ? 32 : 64;
        mma_kernel<<<mma_blocks, 256>>>(xin, U[l], Cv[l], d, (l > 0) ? 1 : 0, N);
        att_kernel<<<att_blocks, 256>>>(src, dst, Cv[l], E);
        edge_kernel<<<edge_blocks, 256>>>(src, dst, E);
        if (l < 2) {
            finalize_kernel<<<fin_blocks, 256>>>(B[l], G[l], BE[l], W[l + 1], hbuf, N, 1);
        } else {
            finalize_kernel<<<fin_blocks, 256>>>(B[l], nullptr, nullptr, nullptr, (float*)d_out, N, 0);
        }
    }
}

// round 13
// speedup vs baseline: 1.0390x; 1.0097x over previous
#include <cuda_runtime.h>
#include <cuda_bf16.h>
#include <cuda_fp16.h>
#include <cstdint>

#define MAXN 25000
#define MAXE 200000

// ---------------- device scratch ----------------
__device__ __align__(16) __half   g_xwh[MAXN * 256];  // per-node linear output, fp16 (edge-only consumer)
__device__ __align__(16) float    g_xu[MAXN * 4];     // per-node u-projection
__device__ __align__(16) float    g_h [MAXN * 64];    // hidden features
__device__ __align__(16) float    g_agg[MAXN * 64];   // scatter accumulator
__device__ __align__(16) uint32_t g_w1f[8192];        // W split hi, fragment-major
__device__ __align__(16) uint32_t g_w2f[8192];        // W split lo, fragment-major
__device__ int      g_deg[MAXN];
__device__ float    g_inv[MAXN];
__device__ double   g_stats[128];   // zero-init; reset by finalize last-block
__device__ unsigned g_fincnt;       // zero-init; reset by finalize last-block
__device__ float    g_s[64];
__device__ float    g_t[64];

// ---------------- W split into fragment-major layout ----------------
__device__ __forceinline__ void wsplit_one(const float* __restrict__ W, int d, int idx) {
    int n = idx >> 6, k = idx & 63;
    float v = (k < d) ? __ldg(W + k * 256 + n) : 0.f;
    __nv_bfloat16 hi = __float2bfloat16(v);
    float lo = v - __bfloat162float(hi);
    int kk = k >> 4, rem = k & 15;
    int word = rem >> 3, r2 = rem & 7, tg = r2 >> 1, half = r2 & 1;
    int u32idx = ((((n >> 3) * 4) + kk) * 32 + (n & 7) * 4 + tg) * 2 + word;
    ((__nv_bfloat16*)g_w1f)[u32idx * 2 + half] = hi;
    ((__nv_bfloat16*)g_w2f)[u32idx * 2 + half] = __float2bfloat16(lo);
}

// ---------------- degree ----------------
__global__ void deg_kernel(const int* __restrict__ dst, int E) {
    int i = blockIdx.x * blockDim.x + threadIdx.x;
    if (i < E) atomicAdd(&g_deg[dst[i]], 1);
}
// inv + layer-0 W split
__global__ void inv_kernel(const float* __restrict__ W0, int d0, int N) {
    int i = blockIdx.x * blockDim.x + threadIdx.x;
    if (i < N) g_inv[i] = 1.f / (float)(g_deg[i] + 1);
    if (blockIdx.x < 64) wsplit_one(W0, d0, blockIdx.x * 256 + threadIdx.x);
}

// ---------------- mma.sync bf16 helper ----------------
__device__ __forceinline__ void mma_bf16(float4& d, const uint32_t* a, const uint32_t* b) {
    asm volatile(
        "mma.sync.aligned.m16n8k16.row.col.f32.bf16.bf16.f32 "
        "{%0,%1,%2,%3}, {%4,%5,%6,%7}, {%8,%9}, {%0,%1,%2,%3};"
        : "+f"(d.x), "+f"(d.y), "+f"(d.z), "+f"(d.w)
        : "r"(a[0]), "r"(a[1]), "r"(a[2]), "r"(a[3]), "r"(b[0]), "r"(b[1]));
}

static constexpr int ROWB = 144;   // A smem row stride (bytes)
static constexpr int XST  = 68;    // xs/selfplane row stride (floats)

// ---------------- fused GEMM kernel: tile = 32 nodes x 256 cols ----------------
__global__ __launch_bounds__(256, 3)
void mma_kernel(const float* __restrict__ x, const float* __restrict__ U,
                const float* __restrict__ cvec, int d, int useBN, int N) {
    __shared__ __align__(16) char  sA1[32 * ROWB];
    __shared__ __align__(16) char  sA2[32 * ROWB];
    __shared__ __align__(16) float xs[32 * XST];   // fp32 x' ; reused as selfplane

    int tid  = threadIdx.x;
    int base = blockIdx.x * 32;

    // ---- load x' (BN-folded) into xs ----
    int c4n = d >> 2;
    int cnt = 32 * c4n;
    for (int f = tid; f < cnt; f += 256) {
        int row = f / c4n, c4 = f - row * c4n;
        float4 v = make_float4(0.f, 0.f, 0.f, 0.f);
        if (base + row < N) v = *(const float4*)(x + (size_t)base * d + (size_t)f * 4);
        if (useBN) {
            int c = c4 * 4;
            v.x = v.x * g_s[c]     + g_t[c];
            v.y = v.y * g_s[c + 1] + g_t[c + 1];
            v.z = v.z * g_s[c + 2] + g_t[c + 2];
            v.w = v.w * g_s[c + 3] + g_t[c + 3];
        }
        *(float4*)(xs + row * XST + c4 * 4) = v;
    }
    if (d == 32) {  // zero upper K half
        int row = tid >> 3, c = 32 + (tid & 7) * 4;
        *(float4*)(xs + row * XST + c) = make_float4(0.f, 0.f, 0.f, 0.f);
    }
    __syncthreads();

    // ---- bf16 split of A into smem ----
    {
        int row = tid >> 3, cg = tid & 7;
        float4 v0 = *(float4*)(xs + row * XST + cg * 8);
        float4 v1 = *(float4*)(xs + row * XST + cg * 8 + 4);
        float vv[8] = {v0.x, v0.y, v0.z, v0.w, v1.x, v1.y, v1.z, v1.w};
        uint32_t hiw[4], low[4];
#pragma unroll
        for (int j = 0; j < 4; j++) {
            __nv_bfloat16 h0 = __float2bfloat16(vv[j * 2]);
            __nv_bfloat16 h1 = __float2bfloat16(vv[j * 2 + 1]);
            __nv_bfloat16 l0 = __float2bfloat16(vv[j * 2]     - __bfloat162float(h0));
            __nv_bfloat16 l1 = __float2bfloat16(vv[j * 2 + 1] - __bfloat162float(h1));
            hiw[j] = (uint32_t)*(uint16_t*)&h0 | ((uint32_t)*(uint16_t*)&h1 << 16);
            low[j] = (uint32_t)*(uint16_t*)&l0 | ((uint32_t)*(uint16_t*)&l1 << 16);
        }
        *(uint4*)(sA1 + row * ROWB + cg * 16) = make_uint4(hiw[0], hiw[1], hiw[2], hiw[3]);
        *(uint4*)(sA2 + row * ROWB + cg * 16) = make_uint4(low[0], low[1], low[2], low[3]);
    }

    // ---- xu = x' @ U (warp w: rows w*4..w*4+4) ----
    {
        int w = tid >> 5, lane = tid & 31;
        float4 u0 = __ldg((const float4*)(U + lane * 4));
        float4 u1 = make_float4(0.f, 0.f, 0.f, 0.f);
        if (d == 64) u1 = __ldg((const float4*)(U + (lane + 32) * 4));
#pragma unroll
        for (int t2 = 0; t2 < 4; t2++) {
            int rloc = w * 4 + t2;
            float v0 = xs[rloc * XST + lane];
            float v1 = xs[rloc * XST + 32 + lane];  // zero when d==32
            float4 p;
            p.x = v0 * u0.x + v1 * u1.x;
            p.y = v0 * u0.y + v1 * u1.y;
            p.z = v0 * u0.z + v1 * u1.z;
            p.w = v0 * u0.w + v1 * u1.w;
#pragma unroll
            for (int off = 16; off >= 1; off >>= 1) {
                p.x += __shfl_xor_sync(0xffffffffu, p.x, off);
                p.y += __shfl_xor_sync(0xffffffffu, p.y, off);
                p.z += __shfl_xor_sync(0xffffffffu, p.z, off);
                p.w += __shfl_xor_sync(0xffffffffu, p.w, off);
            }
            if (lane == 0 && base + rloc < N)
                *(float4*)(g_xu + (size_t)(base + rloc) * 4) = p;
        }
    }
    __syncthreads();

    // ---- MMA mainloop ----
    int w = tid >> 5, lane = tid & 31;
    int g = lane >> 2, tg = lane & 3;
    int q = w & 3, r = w >> 2;
    int rblk = r * 16;

    float4 acc[8];
#pragma unroll
    for (int i = 0; i < 8; i++) acc[i] = make_float4(0.f, 0.f, 0.f, 0.f);

#pragma unroll
    for (int kk = 0; kk < 4; kk++) {
        int k0 = kk * 16;
        int ro0 = (rblk + g) * ROWB, ro1 = (rblk + g + 8) * ROWB;
        int kc0 = (k0 + tg * 2) * 2, kc1 = (k0 + 8 + tg * 2) * 2;
        uint32_t a1f[4], a2f[4];
        a1f[0] = *(const uint32_t*)(sA1 + ro0 + kc0);
        a1f[1] = *(const uint32_t*)(sA1 + ro1 + kc0);
        a1f[2] = *(const uint32_t*)(sA1 + ro0 + kc1);
        a1f[3] = *(const uint32_t*)(sA1 + ro1 + kc1);
        a2f[0] = *(const uint32_t*)(sA2 + ro0 + kc0);
        a2f[1] = *(const uint32_t*)(sA2 + ro1 + kc0);
        a2f[2] = *(const uint32_t*)(sA2 + ro0 + kc1);
        a2f[3] = *(const uint32_t*)(sA2 + ro1 + kc1);
#pragma unroll
        for (int nt = 0; nt < 8; nt++) {
            int fidx = (((q * 8 + nt) * 4) + kk) * 32 + lane;
            uint2 B1 = __ldg((const uint2*)g_w1f + fidx);
            uint2 B2 = __ldg((const uint2*)g_w2f + fidx);
            uint32_t b1[2] = {B1.x, B1.y};
            uint32_t b2[2] = {B2.x, B2.y};
            mma_bf16(acc[nt], a1f, b1);
            mma_bf16(acc[nt], a2f, b1);
            mma_bf16(acc[nt], a1f, b2);
        }
    }

    // ---- write xw (fp16) ----
    int row0 = base + rblk + g;
    int row1 = row0 + 8;
#pragma unroll
    for (int nt = 0; nt < 8; nt++) {
        int col = q * 64 + nt * 8 + tg * 2;
        if (row0 < N)
            *(__half2*)(g_xwh + (size_t)row0 * 256 + col) = __floats2half2_rn(acc[nt].x, acc[nt].y);
        if (row1 < N)
            *(__half2*)(g_xwh + (size_t)row1 * 256 + col) = __floats2half2_rn(acc[nt].z, acc[nt].w);
    }

    // ---- self-loop message -> g_agg init (fp32, exact) ----
    float c0 = __ldg(cvec + 0), c1 = __ldg(cvec + 1);
    float c2 = __ldg(cvec + 2), c3 = __ldg(cvec + 3);
    float mx = fmaxf(fmaxf(c0, c1), fmaxf(c2, c3));
    float e0 = __expf(c0 - mx), e1 = __expf(c1 - mx);
    float e2 = __expf(c2 - mx), e3 = __expf(c3 - mx);
    float sinv = 1.f / (e0 + e1 + e2 + e3);
    float aq = (q == 0 ? e0 : q == 1 ? e1 : q == 2 ? e2 : e3) * sinv;

    __syncthreads();  // xs dead -> reuse as selfplane [32][XST]
    {
        int rw = tid >> 3, c = (tid & 7) * 8;
        *(float4*)(xs + rw * XST + c)     = make_float4(0.f, 0.f, 0.f, 0.f);
        *(float4*)(xs + rw * XST + c + 4) = make_float4(0.f, 0.f, 0.f, 0.f);
    }
    __syncthreads();
#pragma unroll
    for (int qq = 0; qq < 4; qq++) {
        if (q == qq) {
#pragma unroll
            for (int nt = 0; nt < 8; nt++) {
                int cl = nt * 8 + tg * 2;
                float2* p0 = (float2*)(xs + (rblk + g) * XST + cl);
                float2* p1 = (float2*)(xs + (rblk + g + 8) * XST + cl);
                float2 v0 = *p0, v1 = *p1;
                v0.x += aq * acc[nt].x; v0.y += aq * acc[nt].y;
                v1.x += aq * acc[nt].z; v1.y += aq * acc[nt].w;
                *p0 = v0; *p1 = v1;
            }
        }
        __syncthreads();
    }
    {
        int rw = tid >> 3, c = (tid & 7) * 8;
        if (base + rw < N) {
            *(float4*)(g_agg + (size_t)(base + rw) * 64 + c)     = *(float4*)(xs + rw * XST + c);
            *(float4*)(g_agg + (size_t)(base + rw) * 64 + c + 4) = *(float4*)(xs + rw * XST + c + 4);
        }
    }
}

// ---------------- edge kernel: block = 16 edges; phase 1 att in smem, phase 2 gather ----------------
__global__ __launch_bounds__(256)
void edge_kernel(const int* __restrict__ src, const int* __restrict__ dst,
                 const float* __restrict__ cvec, int E) {
    __shared__ int    ss[16];
    __shared__ int    sd[16];
    __shared__ float4 sa[16];

    int tid = threadIdx.x;
    int eb  = blockIdx.x * 16;

    // phase 1: threads 0..15 compute per-edge softmax attention
    if (tid < 16) {
        int e = eb + tid;
        if (e < E) {
            int s  = __ldg(src + e);
            int dv = __ldg(dst + e);
            const float4 us = *(const float4*)(g_xu + s  * 4);
            const float4 ud = *(const float4*)(g_xu + dv * 4);
            float l0 = ud.x - us.x + __ldg(cvec + 0);
            float l1 = ud.y - us.y + __ldg(cvec + 1);
            float l2 = ud.z - us.z + __ldg(cvec + 2);
            float l3 = ud.w - us.w + __ldg(cvec + 3);
            float mx = fmaxf(fmaxf(l0, l1), fmaxf(l2, l3));
            float e0 = __expf(l0 - mx), e1 = __expf(l1 - mx);
            float e2 = __expf(l2 - mx), e3 = __expf(l3 - mx);
            float inv = 1.f / (e0 + e1 + e2 + e3);
            ss[tid] = s;
            sd[tid] = dv;
            sa[tid] = make_float4(e0 * inv, e1 * inv, e2 * inv, e3 * inv);
        }
    }
    __syncthreads();

    // phase 2: 16 lanes per edge gather + scatter
    int sub = tid >> 4;
    int e = eb + sub;
    if (e >= E) return;
    int j = tid & 15;
    int s  = ss[sub];
    int dv = sd[sub];
    float4 a = sa[sub];

    // lane j owns channels [j*4, j*4+4): one uint2 (4 halfs) per head
    const uint2* xwp = (const uint2*)(g_xwh + (size_t)s * 256);
    uint2 u0 = __ldg(xwp + j);          // head 0
    uint2 u1 = __ldg(xwp + 16 + j);     // head 1
    uint2 u2 = __ldg(xwp + 32 + j);     // head 2
    uint2 u3 = __ldg(xwp + 48 + j);     // head 3

    float2 f0a = __half22float2(*(const __half2*)&u0.x), f0b = __half22float2(*(const __half2*)&u0.y);
    float2 f1a = __half22float2(*(const __half2*)&u1.x), f1b = __half22float2(*(const __half2*)&u1.y);
    float2 f2a = __half22float2(*(const __half2*)&u2.x), f2b = __half22float2(*(const __half2*)&u2.y);
    float2 f3a = __half22float2(*(const __half2*)&u3.x), f3b = __half22float2(*(const __half2*)&u3.y);

    float4 m;
    m.x = a.x * f0a.x + a.y * f1a.x + a.z * f2a.x + a.w * f3a.x;
    m.y = a.x * f0a.y + a.y * f1a.y + a.z * f2a.y + a.w * f3a.y;
    m.z = a.x * f0b.x + a.y * f1b.x + a.z * f2b.x + a.w * f3b.x;
    m.w = a.x * f0b.y + a.y * f1b.y + a.z * f2b.y + a.w * f3b.y;

    atomicAdd((float4*)(g_agg + (size_t)dv * 64 + j * 4), m);
}

// ---------------- finalize: mean + bias (+relu + BN stats + s/t fold + next W split) ----------------
__global__ void finalize_kernel(const float* __restrict__ b, const float* __restrict__ gvec,
                                const float* __restrict__ bevec, const float* __restrict__ Wnext,
                                float* __restrict__ out, int N, int doStats) {
    if (doStats && blockIdx.x < 64)
        wsplit_one(Wnext, 64, blockIdx.x * 256 + threadIdx.x);

    int c = threadIdx.x & 63;
    int r = threadIdx.x >> 6;
    float bc = __ldg(b + c);
    float ls = 0.f, lq = 0.f;
    int base = blockIdx.x * 64;

#pragma unroll
    for (int j = 0; j < 16; j++) {
        int i = base + r + j * 4;
        if (i >= N) break;
        float v = g_agg[(size_t)i * 64 + c] * g_inv[i] + bc;
        if (doStats) {
            v = fmaxf(v, 0.f);
            out[(size_t)i * 64 + c] = v;
            ls += v;
            lq += v * v;
        } else {
            out[(size_t)i * 64 + c] = v;
        }
    }

    if (doStats) {
        __shared__ double ss[256], sq[256];
        __shared__ int isLast;
        ss[threadIdx.x] = (double)ls; sq[threadIdx.x] = (double)lq;
        __syncthreads();
        if (threadIdx.x < 128) {
            ss[threadIdx.x] += ss[threadIdx.x + 128];
            sq[threadIdx.x] += sq[threadIdx.x + 128];
        }
        __syncthreads();
        if (threadIdx.x < 64) {
            atomicAdd(&g_stats[c],      ss[threadIdx.x] + ss[threadIdx.x + 64]);
            atomicAdd(&g_stats[64 + c], sq[threadIdx.x] + sq[threadIdx.x + 64]);
        }
        __syncthreads();
        if (threadIdx.x == 0) {
            __threadfence();
            unsigned v = atomicAdd(&g_fincnt, 1u);
            isLast = (v == gridDim.x - 1) ? 1 : 0;
        }
        __syncthreads();
        if (isLast) {
            if (threadIdx.x < 64) {
                __threadfence();
                int cc = threadIdx.x;
                double mean = g_stats[cc] / (double)N;
                double var  = g_stats[64 + cc] / (double)N - mean * mean;
                float s = __ldg(gvec + cc) * rsqrtf((float)var + 1e-5f);
                g_s[cc] = s;
                g_t[cc] = __ldg(bevec + cc) - (float)mean * s;
                g_stats[cc] = 0.0;
                g_stats[64 + cc] = 0.0;
            }
            if (threadIdx.x == 0) g_fincnt = 0u;
        }
    }
}

// ---------------- launch ----------------
extern "C" void kernel_launch(void* const* d_in, const int* in_sizes, int n_in,
                              void* d_out, int out_size) {
    const float* x  = (const float*)d_in[0];
    const int*   ei = (const int*)d_in[1];
    const float* W [3] = {(const float*)d_in[2],  (const float*)d_in[6],  (const float*)d_in[10]};
    const float* U [3] = {(const float*)d_in[3],  (const float*)d_in[7],  (const float*)d_in[11]};
    const float* Cv[3] = {(const float*)d_in[4],  (const float*)d_in[8],  (const float*)d_in[12]};
    const float* B [3] = {(const float*)d_in[5],  (const float*)d_in[9],  (const float*)d_in[13]};
    const float* G [2] = {(const float*)d_in[14], (const float*)d_in[16]};
    const float* BE[2] = {(const float*)d_in[15], (const float*)d_in[17]};

    int N = in_sizes[0] / 32;
    int E = in_sizes[1] / 2;
    const int* src = ei;
    const int* dst = ei + E;

    void *p_deg = nullptr, *p_h = nullptr;
    cudaGetSymbolAddress(&p_deg, g_deg);
    cudaGetSymbolAddress(&p_h,   g_h);
    float* hbuf = (float*)p_h;

    cudaMemsetAsync(p_deg, 0, (size_t)N * sizeof(int));
    deg_kernel<<<(E + 255) / 256, 256>>>(dst, E);
    inv_kernel<<<(N + 255) / 256, 256>>>(W[0], 32, N);   // also splits W0

    int mma_blocks  = (N + 31) / 32;
    int edge_blocks = (E + 15) / 16;
    int fin_blocks  = (N + 63) / 64;

    for (int l = 0; l < 3; l++) {
        const float* xin = (l == 0) ? x : hbuf;
        int d = (l == 0) ? 32 : 64;
        mma_kernel<<<mma_blocks, 256>>>(xin, U[l], Cv[l], d, (l > 0) ? 1 : 0, N);
        edge_kernel<<<edge_blocks, 256>>>(src, dst, Cv[l], E);
        if (l < 2) {
            finalize_kernel<<<fin_blocks, 256>>>(B[l], G[l], BE[l], W[l + 1], hbuf, N, 1);
        } else {
            finalize_kernel<<<fin_blocks, 256>>>(B[l], nullptr, nullptr, nullptr, (float*)d_out, N, 0);
        }
    }
}